// round 3
// baseline (speedup 1.0000x reference)
#include <cuda_runtime.h>
#include <math.h>

// ----------------------------------------------------------------------------
// PHomogeneousAutoencoder: fully fused per-point pipeline.
//   encode: u = unit(x-center); e = unit(MLP_ea(u)); a = softplus(MLP_em(u)[0])
//           w = r^2 * a * e
//   decode: theta = unit(w); r_rec = sqrt(||w||)
//           c = unit(unit(MLP_db(theta)) + MLP_dc([theta, log||w||]))
//           out = center + r_rec * softplus(MLP_dm(theta)[0]) * c
// One block = 128 points, 256 threads. All GEMMs fp32 in shared memory,
// inner loop uses packed fma.rn.f32x2 (FFMA2) for full fp32 rate.
// ----------------------------------------------------------------------------

#define TILE 128
#define HDIM 128
#define AST  132   // padded row stride (floats) for activation buffers

// shared memory layout (in floats)
#define OFF_A   0
#define OFF_B   16896            // 128*132
#define OFF_W2  33792
#define OFF_W1  50176            // 3*128 max
#define OFF_B1  50560
#define OFF_B2  50688
#define OFF_W3  50816            // 128*4 (stride 4, dout<=3)
#define OFF_B3  51328
#define OFF_U   51332            // 128*4
#define OFF_T   51844            // 128*4
#define SMEM_FLOATS 52356
#define SMEM_BYTES  (SMEM_FLOATS * 4)

struct Params {
    const float* x;
    const float* center;
    const float* W1[5];
    const float* b1[5];
    const float* W2[5];
    const float* b2[5];
    const float* W3[5];
    const float* b3[5];
    float* out;
    int n;
};

__device__ __forceinline__ float2 ffma2(float2 a, float2 b, float2 c) {
    float2 d;
    asm("{\n\t"
        ".reg .b64 ra, rb, rc;\n\t"
        "mov.b64 ra, {%2, %3};\n\t"
        "mov.b64 rb, {%4, %5};\n\t"
        "mov.b64 rc, {%6, %7};\n\t"
        "fma.rn.f32x2 rc, ra, rb, rc;\n\t"
        "mov.b64 {%0, %1}, rc;\n\t"
        "}"
        : "=f"(d.x), "=f"(d.y)
        : "f"(a.x), "f"(a.y), "f"(b.x), "f"(b.y), "f"(c.x), "f"(c.y));
    return d;
}

__device__ __forceinline__ float softplus_f(float x) {
    // matches jax.nn.softplus = max(x,0) + log1p(exp(-|x|))
    return fmaxf(x, 0.0f) + log1pf(expf(-fabsf(x)));
}

// Stage one MLP's weights into shared memory. All 256 threads.
__device__ void load_weights(float* sm,
                             const float* __restrict__ W1, const float* __restrict__ b1,
                             const float* __restrict__ W2, const float* __restrict__ b2,
                             const float* __restrict__ W3, const float* __restrict__ b3,
                             int din, int dout) {
    __syncthreads();   // protect previous stage's readers of W3s/B buffer
    int t = threadIdx.x;
    const float4* g = (const float4*)W2;
    float4* s4 = (float4*)(sm + OFF_W2);
#pragma unroll
    for (int i = 0; i < 16; i++) s4[t + 256 * i] = g[t + 256 * i];
    for (int i = t; i < din * HDIM; i += 256) sm[OFF_W1 + i] = W1[i];
    if (t < HDIM) {
        sm[OFF_B1 + t] = b1[t];
        sm[OFF_B2 + t] = b2[t];
#pragma unroll 3
        for (int j = 0; j < dout; j++) sm[OFF_W3 + t * 4 + j] = W3[t * dout + j];
    }
    if (t < dout) sm[OFF_B3 + t] = b3[t];
    __syncthreads();
}

// layer1: A[p][j] = relu(b1[j] + sum_i in[p][i] * W1[i][j]); in stride 4.
template <int DIN>
__device__ void layer1(const float* __restrict__ sm_in, const float* __restrict__ sm) {
    int t = threadIdx.x;
    int p = t >> 1;
    int j0 = (t & 1) * 64;
    float* A = (float*)(sm + OFF_A);
    const float* W1s = sm + OFF_W1;
    const float* B1s = sm + OFF_B1;
    float in[DIN];
#pragma unroll
    for (int i = 0; i < DIN; i++) in[i] = sm_in[p * 4 + i];
#pragma unroll 4
    for (int j = 0; j < 64; j += 4) {
        float4 s = *(const float4*)&B1s[j0 + j];
#pragma unroll
        for (int i = 0; i < DIN; i++) {
            float4 w = *(const float4*)&W1s[i * HDIM + j0 + j];
            s.x = fmaf(in[i], w.x, s.x);
            s.y = fmaf(in[i], w.y, s.y);
            s.z = fmaf(in[i], w.z, s.z);
            s.w = fmaf(in[i], w.w, s.w);
        }
        s.x = fmaxf(s.x, 0.f); s.y = fmaxf(s.y, 0.f);
        s.z = fmaxf(s.z, 0.f); s.w = fmaxf(s.w, 0.f);
        *(float4*)&A[p * AST + j0 + j] = s;
    }
}

// layer2: B[p][j] = relu(b2[j] + sum_k A[p][k] * W2[k][j]).
// 16x16 thread grid, 8 points x 8 outputs per thread, f32x2 accumulators.
__device__ void layer2(float* sm) {
    const float* __restrict__ A = sm + OFF_A;
    const float* __restrict__ W2s = sm + OFF_W2;
    const float* __restrict__ B2s = sm + OFF_B2;
    float* __restrict__ C = sm + OFF_B;
    int t = threadIdx.x;
    int tx = t & 15, ty = t >> 4;
    int p0 = ty * 8, j0 = tx * 8;

    float2 acc[8][4];
    {
        float4 bA = *(const float4*)&B2s[j0];
        float4 bB = *(const float4*)&B2s[j0 + 4];
#pragma unroll
        for (int i = 0; i < 8; i++) {
            acc[i][0] = make_float2(bA.x, bA.y);
            acc[i][1] = make_float2(bA.z, bA.w);
            acc[i][2] = make_float2(bB.x, bB.y);
            acc[i][3] = make_float2(bB.z, bB.w);
        }
    }

#pragma unroll 2
    for (int k0 = 0; k0 < HDIM; k0 += 4) {
        float4 a4[8];
#pragma unroll
        for (int i = 0; i < 8; i++) a4[i] = *(const float4*)&A[(p0 + i) * AST + k0];
#pragma unroll
        for (int kk = 0; kk < 4; kk++) {
            const float* wr = &W2s[(k0 + kk) * HDIM + j0];
            float4 w0 = *(const float4*)wr;
            float4 w1 = *(const float4*)(wr + 4);
            float2 wv[4];
            wv[0] = make_float2(w0.x, w0.y);
            wv[1] = make_float2(w0.z, w0.w);
            wv[2] = make_float2(w1.x, w1.y);
            wv[3] = make_float2(w1.z, w1.w);
#pragma unroll
            for (int i = 0; i < 8; i++) {
                float av = (kk == 0) ? a4[i].x : (kk == 1) ? a4[i].y : (kk == 2) ? a4[i].z : a4[i].w;
                float2 a2 = make_float2(av, av);
#pragma unroll
                for (int jj = 0; jj < 4; jj++) acc[i][jj] = ffma2(a2, wv[jj], acc[i][jj]);
            }
        }
    }

#pragma unroll
    for (int i = 0; i < 8; i++) {
        float* crow = &C[(p0 + i) * AST + j0];
        float4 v0 = make_float4(fmaxf(acc[i][0].x, 0.f), fmaxf(acc[i][0].y, 0.f),
                                fmaxf(acc[i][1].x, 0.f), fmaxf(acc[i][1].y, 0.f));
        float4 v1 = make_float4(fmaxf(acc[i][2].x, 0.f), fmaxf(acc[i][2].y, 0.f),
                                fmaxf(acc[i][3].x, 0.f), fmaxf(acc[i][3].y, 0.f));
        *(float4*)crow = v0;
        *(float4*)(crow + 4) = v1;
    }
}

// layer3: s[j] = b3[j] + sum_k B[p][k] * W3[k][j].  Called by threads t<128 only.
template <int DOUT>
__device__ void layer3(const float* __restrict__ sm, float* s) {
    int p = threadIdx.x;
    const float* Bbuf = sm + OFF_B;
    const float* W3s = sm + OFF_W3;
    const float* B3s = sm + OFF_B3;
#pragma unroll
    for (int j = 0; j < DOUT; j++) s[j] = B3s[j];
#pragma unroll 4
    for (int k0 = 0; k0 < HDIM; k0 += 4) {
        float4 v = *(const float4*)&Bbuf[p * AST + k0];
        float vv[4] = {v.x, v.y, v.z, v.w};
#pragma unroll
        for (int kk = 0; kk < 4; kk++)
#pragma unroll
            for (int j = 0; j < DOUT; j++)
                s[j] = fmaf(vv[kk], W3s[(k0 + kk) * 4 + j], s[j]);
    }
}

__global__ __launch_bounds__(256, 1)
void pha_kernel(Params P) {
    extern __shared__ float sm[];
    int t = threadIdx.x;
    int pg = blockIdx.x * TILE;

    float c0 = P.center[0], c1 = P.center[1], c2 = P.center[2];

    // per-point registers (threads 0..127)
    float rp = 0.f, e0 = 0.f, e1 = 0.f, rrec = 0.f;
    float cb0 = 0.f, cb1 = 0.f, cb2 = 0.f, cc0 = 0.f, cc1 = 0.f, cc2 = 0.f;
    bool live = false;

    // ---- stage 0: u = unit(x - center), rp = r^2 ----
    if (t < TILE) {
        int gp = pg + t;
        live = (gp < P.n);
        float x0 = 0.f, x1 = 0.f, x2 = 0.f;
        if (live) {
            x0 = P.x[gp * 3 + 0] - c0;
            x1 = P.x[gp * 3 + 1] - c1;
            x2 = P.x[gp * 3 + 2] - c2;
        }
        float r = sqrtf(x0 * x0 + x1 * x1 + x2 * x2);
        float inv = 1.0f / (r + 1e-8f);
        sm[OFF_U + t * 4 + 0] = x0 * inv;
        sm[OFF_U + t * 4 + 1] = x1 * inv;
        sm[OFF_U + t * 4 + 2] = x2 * inv;
        sm[OFF_U + t * 4 + 3] = 0.f;
        sm[OFF_T + t * 4 + 0] = 0.f;
        sm[OFF_T + t * 4 + 1] = 0.f;
        sm[OFF_T + t * 4 + 2] = 0.f;
        sm[OFF_T + t * 4 + 3] = 0.f;
        rp = r * r;
    }

    // ---- MLP ea: u -> e (dout=2), then unit ----
    load_weights(sm, P.W1[0], P.b1[0], P.W2[0], P.b2[0], P.W3[0], P.b3[0], 3, 2);
    layer1<3>(sm + OFF_U, sm);
    __syncthreads();
    layer2(sm);
    __syncthreads();
    if (t < TILE) {
        float s[2];
        layer3<2>(sm, s);
        float n = sqrtf(s[0] * s[0] + s[1] * s[1]);
        float inv = 1.0f / (n + 1e-8f);
        e0 = s[0] * inv;
        e1 = s[1] * inv;
    }

    // ---- MLP em: u -> a = softplus(.[0]) ; then w, theta, log r_w ----
    load_weights(sm, P.W1[1], P.b1[1], P.W2[1], P.b2[1], P.W3[1], P.b3[1], 3, 1);
    layer1<3>(sm + OFF_U, sm);
    __syncthreads();
    layer2(sm);
    __syncthreads();
    if (t < TILE) {
        float s[1];
        layer3<1>(sm, s);
        float a = softplus_f(s[0]);
        float w0 = rp * a * e0;
        float w1 = rp * a * e1;
        float rw = sqrtf(w0 * w0 + w1 * w1);
        rrec = sqrtf(rw);                      // rw^(1/P), P=2
        float it = 1.0f / (rw + 1e-8f);
        sm[OFF_T + t * 4 + 0] = w0 * it;       // theta0
        sm[OFF_T + t * 4 + 1] = w1 * it;       // theta1
        sm[OFF_T + t * 4 + 2] = logf(rw + 1e-8f);
    }

    // ---- MLP db: theta -> c_base (dout=3), unit ----
    load_weights(sm, P.W1[2], P.b1[2], P.W2[2], P.b2[2], P.W3[2], P.b3[2], 2, 3);
    layer1<2>(sm + OFF_T, sm);
    __syncthreads();
    layer2(sm);
    __syncthreads();
    if (t < TILE) {
        float s[3];
        layer3<3>(sm, s);
        float n = sqrtf(s[0] * s[0] + s[1] * s[1] + s[2] * s[2]);
        float inv = 1.0f / (n + 1e-8f);
        cb0 = s[0] * inv; cb1 = s[1] * inv; cb2 = s[2] * inv;
    }

    // ---- MLP dc: ci = [theta, log r_w] -> c_corr (dout=3) ----
    load_weights(sm, P.W1[3], P.b1[3], P.W2[3], P.b2[3], P.W3[3], P.b3[3], 3, 3);
    layer1<3>(sm + OFF_T, sm);
    __syncthreads();
    layer2(sm);
    __syncthreads();
    if (t < TILE) {
        float s[3];
        layer3<3>(sm, s);
        cc0 = s[0]; cc1 = s[1]; cc2 = s[2];
    }

    // ---- MLP dm: theta -> b = softplus(.[0]); final output ----
    load_weights(sm, P.W1[4], P.b1[4], P.W2[4], P.b2[4], P.W3[4], P.b3[4], 2, 1);
    layer1<2>(sm + OFF_T, sm);
    __syncthreads();
    layer2(sm);
    __syncthreads();
    if (t < TILE && live) {
        float s[1];
        layer3<1>(sm, s);
        float b = softplus_f(s[0]);
        float v0 = cb0 + cc0, v1 = cb1 + cc1, v2 = cb2 + cc2;
        float n = sqrtf(v0 * v0 + v1 * v1 + v2 * v2);
        float inv = 1.0f / (n + 1e-8f);
        float scale = rrec * b * inv;
        int gp = pg + t;
        P.out[gp * 3 + 0] = c0 + scale * v0;
        P.out[gp * 3 + 1] = c1 + scale * v1;
        P.out[gp * 3 + 2] = c2 + scale * v2;
    }
}

extern "C" void kernel_launch(void* const* d_in, const int* in_sizes, int n_in,
                              void* d_out, int out_size) {
    Params P;
    P.x = (const float*)d_in[0];
    P.center = (const float*)d_in[1];
    for (int m = 0; m < 5; m++) {
        int b = 2 + m * 6;
        P.W1[m] = (const float*)d_in[b + 0];
        P.b1[m] = (const float*)d_in[b + 1];
        P.W2[m] = (const float*)d_in[b + 2];
        P.b2[m] = (const float*)d_in[b + 3];
        P.W3[m] = (const float*)d_in[b + 4];
        P.b3[m] = (const float*)d_in[b + 5];
    }
    P.out = (float*)d_out;
    P.n = in_sizes[0] / 3;

    // Attribute set is idempotent, host-side, and not a stream operation —
    // safe under graph capture. SMEM_BYTES (204.5 KB) < sm_100a 227 KB limit.
    (void)cudaFuncSetAttribute(pha_kernel, cudaFuncAttributeMaxDynamicSharedMemorySize, SMEM_BYTES);
    int grid = (P.n + TILE - 1) / TILE;
    pha_kernel<<<grid, 256, SMEM_BYTES>>>(P);
}

// round 5
// speedup vs baseline: 1.0501x; 1.0501x over previous
#include <cuda_runtime.h>
#include <math.h>

// ----------------------------------------------------------------------------
// PHomogeneousAutoencoder: fully fused per-point pipeline.
// Round-3 change (re-submitted; prior round was an infra failure): layer2
// thread-tile role swap (tx->points, ty->cols) so W2 loads are warp-broadcast
// and A loads are bank-skewed by AST=132 -> all shared traffic conflict-free;
// FMA pipe becomes the critical path.
// ----------------------------------------------------------------------------

#define TILE 128
#define HDIM 128
#define AST  132   // padded row stride (floats); 132 % 32 == 4 -> bank skew

// shared memory layout (in floats)
#define OFF_A   0
#define OFF_B   16896            // 128*132
#define OFF_W2  33792
#define OFF_W1  50176            // 3*128 max
#define OFF_B1  50560
#define OFF_B2  50688
#define OFF_W3  50816            // 128*4 (stride 4, dout<=3)
#define OFF_B3  51328
#define OFF_U   51332            // 128*4
#define OFF_T   51844            // 128*4
#define SMEM_FLOATS 52356
#define SMEM_BYTES  (SMEM_FLOATS * 4)

struct Params {
    const float* x;
    const float* center;
    const float* W1[5];
    const float* b1[5];
    const float* W2[5];
    const float* b2[5];
    const float* W3[5];
    const float* b3[5];
    float* out;
    int n;
};

__device__ __forceinline__ float2 ffma2(float2 a, float2 b, float2 c) {
    float2 d;
    asm("{\n\t"
        ".reg .b64 ra, rb, rc;\n\t"
        "mov.b64 ra, {%2, %3};\n\t"
        "mov.b64 rb, {%4, %5};\n\t"
        "mov.b64 rc, {%6, %7};\n\t"
        "fma.rn.f32x2 rc, ra, rb, rc;\n\t"
        "mov.b64 {%0, %1}, rc;\n\t"
        "}"
        : "=f"(d.x), "=f"(d.y)
        : "f"(a.x), "f"(a.y), "f"(b.x), "f"(b.y), "f"(c.x), "f"(c.y));
    return d;
}

__device__ __forceinline__ float softplus_f(float x) {
    // matches jax.nn.softplus = max(x,0) + log1p(exp(-|x|))
    return fmaxf(x, 0.0f) + log1pf(expf(-fabsf(x)));
}

// Stage one MLP's weights into shared memory. All 256 threads.
__device__ void load_weights(float* sm,
                             const float* __restrict__ W1, const float* __restrict__ b1,
                             const float* __restrict__ W2, const float* __restrict__ b2,
                             const float* __restrict__ W3, const float* __restrict__ b3,
                             int din, int dout) {
    __syncthreads();   // protect previous stage's readers of W3s/B buffer
    int t = threadIdx.x;
    const float4* g = (const float4*)W2;
    float4* s4 = (float4*)(sm + OFF_W2);
#pragma unroll
    for (int i = 0; i < 16; i++) s4[t + 256 * i] = g[t + 256 * i];
    for (int i = t; i < din * HDIM; i += 256) sm[OFF_W1 + i] = W1[i];
    if (t < HDIM) {
        sm[OFF_B1 + t] = b1[t];
        sm[OFF_B2 + t] = b2[t];
#pragma unroll 3
        for (int j = 0; j < dout; j++) sm[OFF_W3 + t * 4 + j] = W3[t * dout + j];
    }
    if (t < dout) sm[OFF_B3 + t] = b3[t];
    __syncthreads();
}

// layer1: A[p][j] = relu(b1[j] + sum_i in[p][i] * W1[i][j]); in stride 4.
template <int DIN>
__device__ void layer1(const float* __restrict__ sm_in, const float* __restrict__ sm) {
    int t = threadIdx.x;
    int p = t >> 1;
    int j0 = (t & 1) * 64;
    float* A = (float*)(sm + OFF_A);
    const float* W1s = sm + OFF_W1;
    const float* B1s = sm + OFF_B1;
    float in[DIN];
#pragma unroll
    for (int i = 0; i < DIN; i++) in[i] = sm_in[p * 4 + i];
#pragma unroll 4
    for (int j = 0; j < 64; j += 4) {
        float4 s = *(const float4*)&B1s[j0 + j];
#pragma unroll
        for (int i = 0; i < DIN; i++) {
            float4 w = *(const float4*)&W1s[i * HDIM + j0 + j];
            s.x = fmaf(in[i], w.x, s.x);
            s.y = fmaf(in[i], w.y, s.y);
            s.z = fmaf(in[i], w.z, s.z);
            s.w = fmaf(in[i], w.w, s.w);
        }
        s.x = fmaxf(s.x, 0.f); s.y = fmaxf(s.y, 0.f);
        s.z = fmaxf(s.z, 0.f); s.w = fmaxf(s.w, 0.f);
        *(float4*)&A[p * AST + j0 + j] = s;
    }
}

// layer2: B[p][j] = relu(b2[j] + sum_k A[p][k] * W2[k][j]).
// Role-swapped 16x16 tile: tx (fast lane) -> 8 points strided by 16,
// ty -> 8 output cols. W2 reads are half-warp broadcast (conflict-free);
// A reads/C writes are conflict-free via the AST=132 bank skew.
__device__ void layer2(float* sm) {
    const float* __restrict__ A = sm + OFF_A;
    const float* __restrict__ W2s = sm + OFF_W2;
    const float* __restrict__ B2s = sm + OFF_B2;
    float* __restrict__ C = sm + OFF_B;
    int t = threadIdx.x;
    int tx = t & 15, ty = t >> 4;
    int j0 = ty * 8;                    // output column group
    // points handled by this thread: p = tx + 16*i, i = 0..7

    float2 acc[8][4];
    {
        float4 bA = *(const float4*)&B2s[j0];
        float4 bB = *(const float4*)&B2s[j0 + 4];
#pragma unroll
        for (int i = 0; i < 8; i++) {
            acc[i][0] = make_float2(bA.x, bA.y);
            acc[i][1] = make_float2(bA.z, bA.w);
            acc[i][2] = make_float2(bB.x, bB.y);
            acc[i][3] = make_float2(bB.z, bB.w);
        }
    }

#pragma unroll 2
    for (int k0 = 0; k0 < HDIM; k0 += 4) {
        float4 a4[8];
#pragma unroll
        for (int i = 0; i < 8; i++) a4[i] = *(const float4*)&A[(tx + 16 * i) * AST + k0];
#pragma unroll
        for (int kk = 0; kk < 4; kk++) {
            const float* wr = &W2s[(k0 + kk) * HDIM + j0];
            float4 w0 = *(const float4*)wr;        // broadcast within half-warp
            float4 w1 = *(const float4*)(wr + 4);
            float2 wv[4];
            wv[0] = make_float2(w0.x, w0.y);
            wv[1] = make_float2(w0.z, w0.w);
            wv[2] = make_float2(w1.x, w1.y);
            wv[3] = make_float2(w1.z, w1.w);
#pragma unroll
            for (int i = 0; i < 8; i++) {
                float av = (kk == 0) ? a4[i].x : (kk == 1) ? a4[i].y : (kk == 2) ? a4[i].z : a4[i].w;
                float2 a2 = make_float2(av, av);
#pragma unroll
                for (int jj = 0; jj < 4; jj++) acc[i][jj] = ffma2(a2, wv[jj], acc[i][jj]);
            }
        }
    }

#pragma unroll
    for (int i = 0; i < 8; i++) {
        float* crow = &C[(tx + 16 * i) * AST + j0];
        float4 v0 = make_float4(fmaxf(acc[i][0].x, 0.f), fmaxf(acc[i][0].y, 0.f),
                                fmaxf(acc[i][1].x, 0.f), fmaxf(acc[i][1].y, 0.f));
        float4 v1 = make_float4(fmaxf(acc[i][2].x, 0.f), fmaxf(acc[i][2].y, 0.f),
                                fmaxf(acc[i][3].x, 0.f), fmaxf(acc[i][3].y, 0.f));
        *(float4*)crow = v0;
        *(float4*)(crow + 4) = v1;
    }
}

// layer3: s[j] = b3[j] + sum_k B[p][k] * W3[k][j].  Called by threads t<128 only.
template <int DOUT>
__device__ void layer3(const float* __restrict__ sm, float* s) {
    int p = threadIdx.x;
    const float* Bbuf = sm + OFF_B;
    const float* W3s = sm + OFF_W3;
    const float* B3s = sm + OFF_B3;
#pragma unroll
    for (int j = 0; j < DOUT; j++) s[j] = B3s[j];
#pragma unroll 4
    for (int k0 = 0; k0 < HDIM; k0 += 4) {
        float4 v = *(const float4*)&Bbuf[p * AST + k0];
        float vv[4] = {v.x, v.y, v.z, v.w};
#pragma unroll
        for (int kk = 0; kk < 4; kk++)
#pragma unroll
            for (int j = 0; j < DOUT; j++)
                s[j] = fmaf(vv[kk], W3s[(k0 + kk) * 4 + j], s[j]);
    }
}

__global__ __launch_bounds__(256, 1)
void pha_kernel(Params P) {
    extern __shared__ float sm[];
    int t = threadIdx.x;
    int pg = blockIdx.x * TILE;

    float c0 = P.center[0], c1 = P.center[1], c2 = P.center[2];

    // per-point registers (threads 0..127)
    float rp = 0.f, e0 = 0.f, e1 = 0.f, rrec = 0.f;
    float cb0 = 0.f, cb1 = 0.f, cb2 = 0.f, cc0 = 0.f, cc1 = 0.f, cc2 = 0.f;
    bool live = false;

    // ---- stage 0: u = unit(x - center), rp = r^2 ----
    if (t < TILE) {
        int gp = pg + t;
        live = (gp < P.n);
        float x0 = 0.f, x1 = 0.f, x2 = 0.f;
        if (live) {
            x0 = P.x[gp * 3 + 0] - c0;
            x1 = P.x[gp * 3 + 1] - c1;
            x2 = P.x[gp * 3 + 2] - c2;
        }
        float r = sqrtf(x0 * x0 + x1 * x1 + x2 * x2);
        float inv = 1.0f / (r + 1e-8f);
        sm[OFF_U + t * 4 + 0] = x0 * inv;
        sm[OFF_U + t * 4 + 1] = x1 * inv;
        sm[OFF_U + t * 4 + 2] = x2 * inv;
        sm[OFF_U + t * 4 + 3] = 0.f;
        sm[OFF_T + t * 4 + 0] = 0.f;
        sm[OFF_T + t * 4 + 1] = 0.f;
        sm[OFF_T + t * 4 + 2] = 0.f;
        sm[OFF_T + t * 4 + 3] = 0.f;
        rp = r * r;
    }

    // ---- MLP ea: u -> e (dout=2), then unit ----
    load_weights(sm, P.W1[0], P.b1[0], P.W2[0], P.b2[0], P.W3[0], P.b3[0], 3, 2);
    layer1<3>(sm + OFF_U, sm);
    __syncthreads();
    layer2(sm);
    __syncthreads();
    if (t < TILE) {
        float s[2];
        layer3<2>(sm, s);
        float n = sqrtf(s[0] * s[0] + s[1] * s[1]);
        float inv = 1.0f / (n + 1e-8f);
        e0 = s[0] * inv;
        e1 = s[1] * inv;
    }

    // ---- MLP em: u -> a = softplus(.[0]) ; then w, theta, log r_w ----
    load_weights(sm, P.W1[1], P.b1[1], P.W2[1], P.b2[1], P.W3[1], P.b3[1], 3, 1);
    layer1<3>(sm + OFF_U, sm);
    __syncthreads();
    layer2(sm);
    __syncthreads();
    if (t < TILE) {
        float s[1];
        layer3<1>(sm, s);
        float a = softplus_f(s[0]);
        float w0 = rp * a * e0;
        float w1 = rp * a * e1;
        float rw = sqrtf(w0 * w0 + w1 * w1);
        rrec = sqrtf(rw);                      // rw^(1/P), P=2
        float it = 1.0f / (rw + 1e-8f);
        sm[OFF_T + t * 4 + 0] = w0 * it;       // theta0
        sm[OFF_T + t * 4 + 1] = w1 * it;       // theta1
        sm[OFF_T + t * 4 + 2] = logf(rw + 1e-8f);
    }

    // ---- MLP db: theta -> c_base (dout=3), unit ----
    load_weights(sm, P.W1[2], P.b1[2], P.W2[2], P.b2[2], P.W3[2], P.b3[2], 2, 3);
    layer1<2>(sm + OFF_T, sm);
    __syncthreads();
    layer2(sm);
    __syncthreads();
    if (t < TILE) {
        float s[3];
        layer3<3>(sm, s);
        float n = sqrtf(s[0] * s[0] + s[1] * s[1] + s[2] * s[2]);
        float inv = 1.0f / (n + 1e-8f);
        cb0 = s[0] * inv; cb1 = s[1] * inv; cb2 = s[2] * inv;
    }

    // ---- MLP dc: ci = [theta, log r_w] -> c_corr (dout=3) ----
    load_weights(sm, P.W1[3], P.b1[3], P.W2[3], P.b2[3], P.W3[3], P.b3[3], 3, 3);
    layer1<3>(sm + OFF_T, sm);
    __syncthreads();
    layer2(sm);
    __syncthreads();
    if (t < TILE) {
        float s[3];
        layer3<3>(sm, s);
        cc0 = s[0]; cc1 = s[1]; cc2 = s[2];
    }

    // ---- MLP dm: theta -> b = softplus(.[0]); final output ----
    load_weights(sm, P.W1[4], P.b1[4], P.W2[4], P.b2[4], P.W3[4], P.b3[4], 2, 1);
    layer1<2>(sm + OFF_T, sm);
    __syncthreads();
    layer2(sm);
    __syncthreads();
    if (t < TILE && live) {
        float s[1];
        layer3<1>(sm, s);
        float b = softplus_f(s[0]);
        float v0 = cb0 + cc0, v1 = cb1 + cc1, v2 = cb2 + cc2;
        float n = sqrtf(v0 * v0 + v1 * v1 + v2 * v2);
        float inv = 1.0f / (n + 1e-8f);
        float scale = rrec * b * inv;
        int gp = pg + t;
        P.out[gp * 3 + 0] = c0 + scale * v0;
        P.out[gp * 3 + 1] = c1 + scale * v1;
        P.out[gp * 3 + 2] = c2 + scale * v2;
    }
}

extern "C" void kernel_launch(void* const* d_in, const int* in_sizes, int n_in,
                              void* d_out, int out_size) {
    Params P;
    P.x = (const float*)d_in[0];
    P.center = (const float*)d_in[1];
    for (int m = 0; m < 5; m++) {
        int b = 2 + m * 6;
        P.W1[m] = (const float*)d_in[b + 0];
        P.b1[m] = (const float*)d_in[b + 1];
        P.W2[m] = (const float*)d_in[b + 2];
        P.b2[m] = (const float*)d_in[b + 3];
        P.W3[m] = (const float*)d_in[b + 4];
        P.b3[m] = (const float*)d_in[b + 5];
    }
    P.out = (float*)d_out;
    P.n = in_sizes[0] / 3;

    (void)cudaFuncSetAttribute(pha_kernel, cudaFuncAttributeMaxDynamicSharedMemorySize, SMEM_BYTES);
    int grid = (P.n + TILE - 1) / TILE;
    pha_kernel<<<grid, 256, SMEM_BYTES>>>(P);
}